// round 17
// baseline (speedup 1.0000x reference)
#include <cuda_runtime.h>
#include <cstdint>
#include <math_constants.h>

// OpeningLoss2D: mean((x - grey_opening_2x2(x))^2) over [8,16,512,512] fp32.
// Separable hmin2 -> vmin2 -> hmax2 -> vmax2 (scipy w=2, edge replicate,
// er-index clamps on dilation).
//
// TMA-bulk producer, 4-row groups: 1024 blocks x 128 threads, 512x64 tiles.
// Ring of 12 tight 512-float row slots (24.6KB). Groups of 4 rows (8KB, one
// mbarrier of 3, barrier g%3, parity (g/3)&1), issued 2 steps ahead by one
// elected thread; ONE try_wait + __syncthreads per 4 rows (17 syncs vs 33).
// Row p <-> slot p%12. Groups 0 (top clamp) and 16 (2 rows, bottom clamp)
// are the only clamped issues; groups 1..15 stream via a running pointer.
// Right-edge dilation clamp = -inf select on the last thread.

#define FULLMASK 0xffffffffu

static const int Hc = 512;
static const int Wc = 512;
static const int TR = 64;
static const int NBLK = 1024;          // 128 slices * 8 row-tiles

__device__ float g_partials[NBLK];
__device__ unsigned int g_count = 0;

__device__ __forceinline__ void mbar_init(uint32_t addr, uint32_t cnt) {
    asm volatile("mbarrier.init.shared.b64 [%0], %1;" :: "r"(addr), "r"(cnt) : "memory");
}
__device__ __forceinline__ void mbar_expect(uint32_t addr, uint32_t bytes) {
    asm volatile("mbarrier.arrive.expect_tx.shared.b64 _, [%0], %1;"
                 :: "r"(addr), "r"(bytes) : "memory");
}
__device__ __forceinline__ void mbar_wait(uint32_t addr, uint32_t parity) {
    asm volatile(
        "{\n\t"
        ".reg .pred P;\n\t"
        "WL_%=:\n\t"
        "mbarrier.try_wait.parity.acquire.cta.shared::cta.b64 P, [%0], %1, 0x989680;\n\t"
        "@P bra WD_%=;\n\t"
        "bra WL_%=;\n\t"
        "WD_%=:\n\t"
        "}"
        :: "r"(addr), "r"(parity) : "memory");
}
__device__ __forceinline__ void bulk2k(uint32_t dst, const float* src, uint32_t mba) {
    asm volatile(
        "cp.async.bulk.shared::cluster.global.mbarrier::complete_tx::bytes "
        "[%0], [%1], 2048, [%2];"
        :: "r"(dst), "l"(src), "r"(mba) : "memory");
}

__global__ void __launch_bounds__(128, 9)
opening_kernel(const float* __restrict__ X, float* __restrict__ out) {
    __shared__ __align__(16) float ring[12 * Wc + 16];  // +16 fl OOB-read guard
    __shared__ __align__(8) unsigned long long mbar[3];
    __shared__ float wsum[4];
    __shared__ bool amLast;

    const int t      = threadIdx.x;       // 0..127
    const int lane   = t & 31;
    const int warpId = t >> 5;
    const int tile   = blockIdx.x;        // 0..1023
    const int slice  = tile >> 3;         // 0..127
    const int r0     = (tile & 7) * TR;
    const float* S   = X + (size_t)slice * (Hc * Wc);
    const int c0     = t << 2;            // first owned column (0..508)
    const bool isL0  = (lane == 0);
    const bool isL31 = (lane == 31);
    const bool lastT = (t == 127);
    const int lcol   = max(c0 - 1, 0);    // left clamp (t=0 -> col 0)

    const uint32_t sring = (uint32_t)__cvta_generic_to_shared(&ring[0]);
    const uint32_t mb    = (uint32_t)__cvta_generic_to_shared(&mbar[0]);

    if (t == 0) {
        mbar_init(mb + 0, 1); mbar_init(mb + 8, 1); mbar_init(mb + 16, 1);
    }
    __syncthreads();

    #define LOADROW(sl)                                                       \
        const float* _row = &ring[(sl) * Wc];                                 \
        float4 _q = *reinterpret_cast<const float4*>(_row + c0);              \
        float _L = __shfl_up_sync(FULLMASK, _q.w, 1);                         \
        float _R = __shfl_down_sync(FULLMASK, _q.x, 1);                       \
        if (isL0)  _L = _row[lcol];                                           \
        if (isL31) _R = lastT ? -CUDART_INF_F : _row[c0 + 4];                 \
        float _h0 = fminf(_L,  _q.x), _h1 = fminf(_q.x, _q.y);                \
        float _h2 = fminf(_q.y, _q.z), _h3 = fminf(_q.z, _q.w);               \
        float _h4 = fminf(_q.w, _R);

    #define FULLROW(sl) do {                                                  \
        LOADROW(sl)                                                            \
        float _e0 = fminf(hp0,_h0), _e1 = fminf(hp1,_h1), _e2 = fminf(hp2,_h2);\
        float _e3 = fminf(hp3,_h3), _e4 = fminf(hp4,_h4);                      \
        float _M0 = fmaxf(_e0,_e1), _M1 = fmaxf(_e1,_e2);                      \
        float _M2 = fmaxf(_e2,_e3), _M3 = fmaxf(_e3,_e4);                      \
        float _s0 = fmaxf(Mp0,_M0), _s1 = fmaxf(Mp1,_M1);                      \
        float _s2 = fmaxf(Mp2,_M2), _s3 = fmaxf(Mp3,_M3);                      \
        float _d0 = xp0 - _s0, _d1 = xp1 - _s1;                                \
        float _d2 = xp2 - _s2, _d3 = xp3 - _s3;                                \
        acc0 = fmaf(_d0,_d0,acc0); acc1 = fmaf(_d1,_d1,acc1);                  \
        acc0 = fmaf(_d2,_d2,acc0); acc1 = fmaf(_d3,_d3,acc1);                  \
        hp0=_h0; hp1=_h1; hp2=_h2; hp3=_h3; hp4=_h4;                           \
        Mp0=_M0; Mp1=_M1; Mp2=_M2; Mp3=_M3;                                    \
        xp0=_q.x; xp1=_q.y; xp2=_q.z; xp3=_q.w;                                \
    } while (0)

    // hot group issue: 4 rows from running pointer gsrc -> slots s0..s0+3
    #define HISSUE4(bi, s0) do { if (t == 0) {                                 \
        uint32_t _m = mb + (bi) * 8;                                           \
        mbar_expect(_m, 8192);                                                 \
        bulk2k(sring + (uint32_t)((s0)     * 2048), gsrc,          _m);        \
        bulk2k(sring + (uint32_t)(((s0)+1) * 2048), gsrc +     Wc, _m);        \
        bulk2k(sring + (uint32_t)(((s0)+2) * 2048), gsrc + 2 * Wc, _m);        \
        bulk2k(sring + (uint32_t)(((s0)+3) * 2048), gsrc + 3 * Wc, _m);        \
    } gsrc += 4 * Wc; } while (0)

    // step: wait group's barrier, block-barrier, optional issue, 4 rows
    #define STEP4(bi, par, ISSUE_STMT, RS) do {                                \
        if (t < 32) mbar_wait(mb + (bi) * 8, (uint32_t)(par));                 \
        __syncthreads();                                                       \
        ISSUE_STMT;                                                            \
        FULLROW(RS); FULLROW((RS)+1); FULLROW((RS)+2); FULLROW((RS)+3);        \
    } while (0)

    float hp0, hp1, hp2, hp3, hp4;
    float Mp0, Mp1, Mp2, Mp3;
    float xp0, xp1, xp2, xp3;
    float acc0 = 0.f, acc1 = 0.f;

    // ---- prologue: group 0 (rows 0..3, top clamp on row 0) -> b0, slots 0-3
    if (t == 0) {
        mbar_expect(mb + 0, 8192);
        bulk2k(sring +    0, S + (size_t)max(r0 - 1, 0) * Wc, mb);
        bulk2k(sring + 2048, S + (size_t)(r0    ) * Wc, mb);
        bulk2k(sring + 4096, S + (size_t)(r0 + 1) * Wc, mb);
        bulk2k(sring + 6144, S + (size_t)(r0 + 2) * Wc, mb);
    }
    // group 1 (rows 4..7 = x rows r0+3..r0+6, clamp-free for all tiles)
    const float* gsrc = S + (size_t)(r0 + 3) * Wc;
    HISSUE4(1, 4);

    // ---- step 0 (group 0, b0 par0): issue group 2 (b2, slots 8-11);
    // rows 0..3 with p=0 (hm only) and p=1 (no smooth) peeled.
    if (t < 32) mbar_wait(mb + 0, 0u);
    __syncthreads();
    HISSUE4(2, 8);
    {   LOADROW(0)
        hp0=_h0; hp1=_h1; hp2=_h2; hp3=_h3; hp4=_h4;
    }
    {   LOADROW(1)
        float _e0 = fminf(hp0,_h0), _e1 = fminf(hp1,_h1), _e2 = fminf(hp2,_h2);
        float _e3 = fminf(hp3,_h3), _e4 = fminf(hp4,_h4);
        Mp0 = fmaxf(_e0,_e1); Mp1 = fmaxf(_e1,_e2);
        Mp2 = fmaxf(_e2,_e3); Mp3 = fmaxf(_e3,_e4);
        hp0=_h0; hp1=_h1; hp2=_h2; hp3=_h3; hp4=_h4;
        xp0=_q.x; xp1=_q.y; xp2=_q.z; xp3=_q.w;
    }
    FULLROW(2);
    FULLROW(3);

    // ---- steps 1..12: two super-iterations of 6 (barrier cycle 3 x parity 2).
    // Step s waits group s (b s%3, par (s/3)&1), issues group s+2 into the
    // slots read at step s-1 (block-barrier-ordered). Issued groups 3..14 =
    // rows 12..59 = x rows r0+11..r0+58 <= 506: clamp-free for every tile.
    #pragma unroll 1
    for (int i = 0; i < 2; ++i) {
        STEP4(1, 0, HISSUE4(0, 0), 4);    // s=6i+1
        STEP4(2, 0, HISSUE4(1, 4), 8);    // s=6i+2
        STEP4(0, 1, HISSUE4(2, 8), 0);    // s=6i+3
        STEP4(1, 1, HISSUE4(0, 0), 4);    // s=6i+4
        STEP4(2, 1, HISSUE4(1, 4), 8);    // s=6i+5
        STEP4(0, 0, HISSUE4(2, 8), 0);    // s=6i+6
    }

    // ---- tail.
    // step 13 (g13, b1 par0): issue group 15 (b0, slots 0-3, rows 60..63 =
    // x rows r0+59..r0+62 <= 510: clamp-free); process rows 52..55.
    STEP4(1, 0, HISSUE4(0, 0), 4);
    // step 14 (g14, b2 par0): issue group 16 (b1, slots 4,5, rows 64,65 =
    // x rows min(r0+63,511), min(r0+64,511); 4KB); process rows 56..59.
    STEP4(2, 0,
        do { if (t == 0) {
            uint32_t _m = mb + 8;
            mbar_expect(_m, 4096);
            bulk2k(sring + 4 * 2048, S + (size_t)min(r0 + 63, Hc - 1) * Wc, _m);
            bulk2k(sring + 5 * 2048, S + (size_t)min(r0 + 64, Hc - 1) * Wc, _m);
        } } while (0), 8);
    // step 15 (g15, b0 par1): rows 60..63 (slots 0-3)
    STEP4(0, 1, , 0);
    // step 16 (g16, b1 par1): rows 64,65 (slots 4,5), bottom boundary
    if (t < 32) mbar_wait(mb + 8, 1u);
    __syncthreads();
    FULLROW(4);
    if (r0 + TR >= Hc) {
        // er row 512 doesn't exist: smooth(511) = hM(511) = Mp
        float _d0 = xp0 - Mp0, _d1 = xp1 - Mp1;
        float _d2 = xp2 - Mp2, _d3 = xp3 - Mp3;
        acc0 = fmaf(_d0,_d0,acc0); acc1 = fmaf(_d1,_d1,acc1);
        acc0 = fmaf(_d2,_d2,acc0); acc1 = fmaf(_d3,_d3,acc1);
    } else {
        FULLROW(5);
    }
    #undef STEP4
    #undef HISSUE4
    #undef LOADROW
    #undef FULLROW

    float acc = acc0 + acc1;
    #pragma unroll
    for (int off = 16; off; off >>= 1)
        acc += __shfl_down_sync(FULLMASK, acc, off);
    if (lane == 0) wsum[warpId] = acc;
    __syncthreads();
    if (t == 0) {
        float s = wsum[0] + wsum[1] + wsum[2] + wsum[3];
        g_partials[blockIdx.x] = s;
        __threadfence();
        unsigned int old = atomicAdd(&g_count, 1u);
        amLast = (old == (unsigned)(NBLK - 1));
    }
    __syncthreads();

    if (amLast) {
        __shared__ float sh[128];
        float s = 0.f;
        for (int i = t; i < NBLK; i += 128) s += g_partials[i];
        sh[t] = s;
        __syncthreads();
        #pragma unroll
        for (int off = 64; off; off >>= 1) {
            if (t < off) sh[t] += sh[t + off];
            __syncthreads();
        }
        if (t == 0) {
            out[0] = sh[0] * (1.0f / 33554432.0f);  // mean over 8*16*512*512
            g_count = 0;                            // deterministic replays
        }
    }
}

extern "C" void kernel_launch(void* const* d_in, const int* in_sizes, int n_in,
                              void* d_out, int out_size) {
    const float* X = (const float*)d_in[0];
    opening_kernel<<<NBLK, 128>>>(X, (float*)d_out);
}